// round 15
// baseline (speedup 1.0000x reference)
#include <cuda_runtime.h>
#include <cuda_bf16.h>
#include <cstdint>

#define TSTEPS 20
#define NROWS  32768
#define DEMB   64
#define DH     128
#define DOUT   5
#define GATES  512
#define KTOT   192
#define MROWS  64          // rows per tile
#define NTILE  512         // 32768/64
#define NQCTA  37          // CTAs per quarter (148 = 4*37)
#define NTHREADS 512

// ---- smem layout (bytes) ----
#define OFF_W    0         // 98304 : quarter weights, hi [0,49152) lo [49152,98304)
#define WHALF    49152
#define OFF_A    98304     // 2 buffers x 49152 (hi 24576 | lo 24576)
#define ABUF     49152
#define AHALF    24576
#define OFF_BIAS 196608    // 512 B : quarter biases [gate*32+dl]
#define OFF_WOUT 197120    // 640 B : quarter W_out [dl*5+q]
#define SMEM_BYTES 197760

// Persistent state + packed weights (allowed scratch: __device__ globals)
__device__ float g_hA[(size_t)NROWS * DH];
__device__ float g_hB[(size_t)NROWS * DH];
__device__ float g_c [(size_t)NROWS * DH];
__device__ int   g_mask_is_i32;
// Per-quarter packed W^T hi/lo: [4 quarters][3 k-atoms][128 c][64 k] bf16, SW128 swizzled
__device__ __nv_bfloat16 g_wq_hi[4 * 128 * KTOT];
__device__ __nv_bfloat16 g_wq_lo[4 * 128 * KTOT];

__device__ __forceinline__ uint32_t smem_u32(const void* p) {
    uint32_t a;
    asm("{ .reg .u64 t; cvta.to.shared.u64 t, %1; cvt.u32.u64 %0, t; }" : "=r"(a) : "l"(p));
    return a;
}
__device__ __forceinline__ void ldsm_x4(uint32_t* r, uint32_t addr) {
    asm volatile("ldmatrix.sync.aligned.m8n8.x4.shared.b16 {%0,%1,%2,%3}, [%4];"
        : "=r"(r[0]), "=r"(r[1]), "=r"(r[2]), "=r"(r[3]) : "r"(addr));
}
__device__ __forceinline__ void mma16816(float* c, const uint32_t* a, uint32_t b0, uint32_t b1) {
    asm volatile("mma.sync.aligned.m16n8k16.row.col.f32.bf16.bf16.f32 "
        "{%0,%1,%2,%3}, {%4,%5,%6,%7}, {%8,%9}, {%0,%1,%2,%3};"
        : "+f"(c[0]), "+f"(c[1]), "+f"(c[2]), "+f"(c[3])
        : "r"(a[0]), "r"(a[1]), "r"(a[2]), "r"(a[3]), "r"(b0), "r"(b1));
}
__device__ __forceinline__ void cp_async16(uint32_t dst, const void* src) {
    asm volatile("cp.async.cg.shared.global [%0], [%1], 16;" :: "r"(dst), "l"(src));
}
__device__ __forceinline__ float sigf(float x) { return 1.0f / (1.0f + __expf(-x)); }
__device__ __forceinline__ float tanhf_fast(float x) {
    x = fminf(fmaxf(x, -30.0f), 30.0f);
    float e = __expf(-2.0f * x);
    return (1.0f - e) / (1.0f + e);
}

__global__ void detect_mask_kernel(const unsigned char* __restrict__ m) {
    if (threadIdx.x == 0 && blockIdx.x == 0) {
        int is_i32 = 1;
        for (int i = 0; i < 4096; ++i)
            if ((i & 3) != 0 && m[i] != 0) { is_i32 = 0; break; }
        g_mask_is_i32 = is_i32;
    }
}
__global__ void init_state(const float* __restrict__ h0, const float* __restrict__ c0) {
    int i = blockIdx.x * blockDim.x + threadIdx.x;
    ((float4*)g_hA)[i] = ((const float4*)h0)[i];
    ((float4*)g_c)[i]  = ((const float4*)c0)[i];
}
__global__ void zero_out(float* __restrict__ out) {
    ((float4*)out)[blockIdx.x * blockDim.x + threadIdx.x] = make_float4(0.f, 0.f, 0.f, 0.f);
}

// Pack weights: quarter Q, packed col c (0..127), k (0..191).
// c decode: nw=c>>5, nb=(c&31)>>3, inner=c&7, q=inner>>1, hilo=inner&1;
//   dl = 8*nw + 4*(nb>>1) + q ; gate = 2*(nb&1) + hilo ; n = gate*128 + 32Q + dl
__global__ void prep_weights(const float* __restrict__ W_ih, const float* __restrict__ W_hh) {
    int idx = blockIdx.x * blockDim.x + threadIdx.x;   // 0 .. 98303
    int Q = idx / (128 * KTOT);
    int r = idx % (128 * KTOT);
    int c = r / KTOT;
    int k = r % KTOT;
    int nw = c >> 5, nb = (c & 31) >> 3, inner = c & 7;
    int q = inner >> 1, hilo = inner & 1;
    int dl = 8 * nw + 4 * (nb >> 1) + q;
    int gate = 2 * (nb & 1) + hilo;
    int n = gate * 128 + 32 * Q + dl;
    float w = (k < DEMB) ? W_ih[(size_t)k * GATES + n]
                         : W_hh[(size_t)(k - DEMB) * GATES + n];
    __nv_bfloat16 hi = __float2bfloat16(w);
    __nv_bfloat16 lo = __float2bfloat16(w - __bfloat162float(hi));
    uint32_t off = (uint32_t)(k >> 6) * 16384u + (uint32_t)c * 128u + (uint32_t)(k & 63) * 2u;
    uint32_t sw = off ^ ((off >> 3) & 0x70);
    g_wq_hi[(size_t)Q * (128 * KTOT) + (sw >> 1)] = hi;
    g_wq_lo[(size_t)Q * (128 * KTOT) + (sw >> 1)] = lo;
}

__global__ __launch_bounds__(NTHREADS, 1)
void vlstm_step(const float* __restrict__ nodes_t,
                const unsigned char* __restrict__ mask_base, int tstep,
                const float* __restrict__ W_embed, const float* __restrict__ b_embed,
                const float* __restrict__ b_ih,    const float* __restrict__ b_hh,
                const float* __restrict__ W_out,   const float* __restrict__ b_out,
                float* __restrict__ out_t,
                float* __restrict__ h_fin, float* __restrict__ c_fin,
                int is_last)
{
    extern __shared__ __align__(1024) char sm[];
    const uint32_t smb = smem_u32(sm);
    const int tid  = threadIdx.x;
    const int warp = tid >> 5;
    const int lane = tid & 31;
    const int Q     = blockIdx.x & 3;
    const int start = blockIdx.x >> 2;
    const int mg = warp >> 2;         // m-group: rows [16mg, 16mg+16)
    const int nw = warp & 3;          // n-warp : packed cols [32nw, 32nw+32)
    float* bias_s = (float*)(sm + OFF_BIAS);
    float* wout_s = (float*)(sm + OFF_WOUT);

    const float* h_in  = (tstep & 1) ? g_hB : g_hA;
    float*       h_out = is_last ? h_fin : ((tstep & 1) ? g_hA : g_hB);
    const int    msz   = g_mask_is_i32 ? 4 : 1;

    // ---- weight quarter -> smem (98304 B, 12x16B per thread), async
    {
        const char* srcH = (const char*)g_wq_hi + (size_t)Q * WHALF + (size_t)tid * 16;
        const char* srcL = (const char*)g_wq_lo + (size_t)Q * WHALF + (size_t)tid * 16;
        uint32_t dst = smb + OFF_W + (uint32_t)tid * 16;
        #pragma unroll
        for (int j = 0; j < 6; ++j) {
            cp_async16(dst + j * 8192,         srcH + (size_t)j * 8192);
            cp_async16(dst + WHALF + j * 8192, srcL + (size_t)j * 8192);
        }
        asm volatile("cp.async.commit_group;");
    }
    if (tid < 128) {
        int g = tid >> 5, dl = tid & 31;
        bias_s[tid] = b_ih[g * 128 + 32 * Q + dl] + b_hh[g * 128 + 32 * Q + dl];
    }
    if (tid < 32 * DOUT)
        wout_s[tid] = W_out[(size_t)(32 * Q + tid / DOUT) * DOUT + tid % DOUT];

    // ---- A staging: row rr = tid>>3, k-slice sl = tid&7 covers [24sl, 24sl+24)
    auto stage_A = [&](int buf, int row0) {
        const int rr = tid >> 3, sl = tid & 7;
        const int gr = row0 + rr;
        float2 x = *(const float2*)(nodes_t + (size_t)gr * 2);
        char* bh = sm + OFF_A + buf * ABUF;
        const int k0 = sl * 24;
        #pragma unroll
        for (int ii = 0; ii < 24; ii += 2) {
            int k = k0 + ii;
            float v0, v1;
            if (k < DEMB) {
                v0 = fmaxf(fmaf(x.x, W_embed[k],   fmaf(x.y, W_embed[DEMB + k],   b_embed[k])),   0.f);
                v1 = fmaxf(fmaf(x.x, W_embed[k+1], fmaf(x.y, W_embed[DEMB + k+1], b_embed[k+1])), 0.f);
            } else {
                float2 hv = *(const float2*)(h_in + (size_t)gr * DH + (k - DEMB));
                v0 = hv.x; v1 = hv.y;
            }
            __nv_bfloat16 h0 = __float2bfloat16(v0), h1 = __float2bfloat16(v1);
            __nv_bfloat16 l0 = __float2bfloat16(v0 - __bfloat162float(h0));
            __nv_bfloat16 l1 = __float2bfloat16(v1 - __bfloat162float(h1));
            uint32_t off = (uint32_t)(k >> 6) * 8192u + (uint32_t)rr * 128u + (uint32_t)(k & 63) * 2u;
            uint32_t sw = off ^ ((off >> 3) & 0x70);
            __nv_bfloat162 ph; ph.x = h0; ph.y = h1;
            __nv_bfloat162 pl; pl.x = l0; pl.y = l1;
            *(__nv_bfloat162*)(bh + sw)         = ph;
            *(__nv_bfloat162*)(bh + AHALF + sw) = pl;
        }
    };

    // ---- LSTM epilogue for a finished tile
    auto epilogue = [&](float (&acc)[4][4], int row0) {
        #pragma unroll
        for (int j = 0; j < 2; ++j) {
            const int r    = 16 * mg + 8 * j + (lane >> 2);
            const int grow = row0 + r;
            const bool m = mask_base[((size_t)tstep * NROWS + grow) * (size_t)msz] != 0;
            float pr[DOUT] = {0.f, 0.f, 0.f, 0.f, 0.f};
            #pragma unroll
            for (int hp = 0; hp < 2; ++hp) {
                const int dl = 8 * nw + 4 * hp + (lane & 3);
                const int d  = 32 * Q + dl;
                float iv = acc[2 * hp][2 * j],     fv = acc[2 * hp][2 * j + 1];
                float gv = acc[2 * hp + 1][2 * j], ov = acc[2 * hp + 1][2 * j + 1];
                float co = g_c[(size_t)grow * DH + d];
                float cn = sigf(fv) * co + sigf(iv) * tanhf_fast(gv);
                float hn = sigf(ov) * tanhf_fast(cn);
                float ho = h_in[(size_t)grow * DH + d];
                h_out[(size_t)grow * DH + d] = m ? hn : ho;
                if (is_last) c_fin[(size_t)grow * DH + d] = m ? cn : co;
                else if (m)  g_c[(size_t)grow * DH + d] = cn;
                if (m) {
                    #pragma unroll
                    for (int q = 0; q < DOUT; ++q)
                        pr[q] = fmaf(hn, wout_s[dl * DOUT + q], pr[q]);
                }
            }
            #pragma unroll
            for (int q = 0; q < DOUT; ++q) {
                pr[q] += __shfl_xor_sync(0xFFFFFFFF, pr[q], 1);
                pr[q] += __shfl_xor_sync(0xFFFFFFFF, pr[q], 2);
            }
            if (m && (lane & 3) == 0) {
                #pragma unroll
                for (int q = 0; q < DOUT; ++q)
                    atomicAdd(&out_t[(size_t)grow * DOUT + q],
                              pr[q] + ((nw == 0 && Q == 0) ? b_out[q] : 0.f));
            }
        }
    };

    // per-lane invariant ldsm address parts
    const uint32_t aoffL = (uint32_t)(16 * mg + (lane & 15)) * 128u + (uint32_t)((lane >> 4) * 16);
    const int grp = lane >> 3;
    const uint32_t boffL = (uint32_t)(32 * nw + 8 * (grp >> 1) + (lane & 7)) * 128u
                         + (uint32_t)((grp & 1) * 16);
    const int dlq = lane & 3;

    // ---- MMA of one tile (acc bias-initialized here)
    auto mma_tile = [&](float (&acc)[4][4], int buf) {
        #pragma unroll
        for (int nb = 0; nb < 4; ++nb) {
            int dl = 8 * nw + 4 * (nb >> 1) + dlq;
            float b0 = bias_s[(2 * (nb & 1) + 0) * 32 + dl];
            float b1 = bias_s[(2 * (nb & 1) + 1) * 32 + dl];
            acc[nb][0] = b0; acc[nb][1] = b1; acc[nb][2] = b0; acc[nb][3] = b1;
        }
        const uint32_t abase = smb + OFF_A + (uint32_t)buf * ABUF;
        const uint32_t wbase = smb + OFF_W;
        #pragma unroll
        for (int ks = 0; ks < 12; ++ks) {
            uint32_t kadd = (uint32_t)(ks >> 2);
            uint32_t jadd = (uint32_t)(ks & 3) * 32u;
            uint32_t offa = aoffL + kadd * 8192u + jadd;
            uint32_t swa  = offa ^ ((offa >> 3) & 0x70);
            uint32_t offb = boffL + kadd * 16384u + jadd;
            uint32_t swb  = offb ^ ((offb >> 3) & 0x70);
            uint32_t ah[4], al[4], b0h[4], b1h[4], b0l[4], b1l[4];
            ldsm_x4(ah,  abase + swa);
            ldsm_x4(al,  abase + swa + AHALF);
            ldsm_x4(b0h, wbase + swb);
            ldsm_x4(b1h, wbase + swb + 2048);           // +16 packed cols (swizzle-invariant)
            ldsm_x4(b0l, wbase + swb + WHALF);
            ldsm_x4(b1l, wbase + swb + 2048 + WHALF);
            // term 0: Ah @ Wh
            mma16816(acc[0], ah, b0h[0], b0h[1]);
            mma16816(acc[1], ah, b0h[2], b0h[3]);
            mma16816(acc[2], ah, b1h[0], b1h[1]);
            mma16816(acc[3], ah, b1h[2], b1h[3]);
            // term 1: Ah @ Wl
            mma16816(acc[0], ah, b0l[0], b0l[1]);
            mma16816(acc[1], ah, b0l[2], b0l[3]);
            mma16816(acc[2], ah, b1l[0], b1l[1]);
            mma16816(acc[3], ah, b1l[2], b1l[3]);
            // term 2: Al @ Wh
            mma16816(acc[0], al, b0h[0], b0h[1]);
            mma16816(acc[1], al, b0h[2], b0h[3]);
            mma16816(acc[2], al, b1h[0], b1h[1]);
            mma16816(acc[3], al, b1h[2], b1h[3]);
        }
    };

    // ---- prologue: stage first tile, wait for weights
    stage_A(0, start * MROWS);
    asm volatile("cp.async.wait_group 0;");
    __syncthreads();

    // ---- persistent tile loop (double-buffered A)
    float acc[4][4];
    int i = 0;
    for (int tile = start; tile < NTILE; tile += NQCTA, ++i) {
        const int buf = i & 1;
        mma_tile(acc, buf);
        if (tile + NQCTA < NTILE) stage_A(buf ^ 1, (tile + NQCTA) * MROWS);
        epilogue(acc, tile * MROWS);
        __syncthreads();
    }
}

extern "C" void kernel_launch(void* const* d_in, const int* in_sizes, int n_in,
                              void* d_out, int out_size) {
    const float*         nodes   = (const float*)d_in[0];
    const unsigned char* mask    = (const unsigned char*)d_in[1];
    const float*         h0      = (const float*)d_in[2];
    const float*         c0      = (const float*)d_in[3];
    const float*         W_embed = (const float*)d_in[4];
    const float*         b_embed = (const float*)d_in[5];
    const float*         W_ih    = (const float*)d_in[6];
    const float*         b_ih    = (const float*)d_in[7];
    const float*         W_hh    = (const float*)d_in[8];
    const float*         b_hh    = (const float*)d_in[9];
    const float*         W_out   = (const float*)d_in[10];
    const float*         b_out   = (const float*)d_in[11];

    float* out   = (float*)d_out;
    float* h_fin = out + (size_t)TSTEPS * NROWS * DOUT;
    float* c_fin = h_fin + (size_t)NROWS * DH;

    static int smem_set = 0;
    if (!smem_set) {
        cudaFuncSetAttribute(vlstm_step,
                             cudaFuncAttributeMaxDynamicSharedMemorySize, SMEM_BYTES);
        smem_set = 1;
    }

    detect_mask_kernel<<<1, 32>>>(mask);
    init_state<<<(NROWS * DH / 4) / 256, 256>>>(h0, c0);
    prep_weights<<<4 * 128 * KTOT / 256, 256>>>(W_ih, W_hh);
    zero_out<<<(TSTEPS * NROWS * DOUT / 4) / 256, 256>>>(out);
    for (int t = 0; t < TSTEPS; ++t) {
        vlstm_step<<<148, NTHREADS, SMEM_BYTES>>>(
            nodes + (size_t)t * NROWS * 2,
            mask, t,
            W_embed, b_embed, b_ih, b_hh, W_out, b_out,
            out + (size_t)t * NROWS * DOUT,
            h_fin, c_fin,
            (t == TSTEPS - 1) ? 1 : 0);
    }
}